// round 1
// baseline (speedup 1.0000x reference)
#include <cuda_runtime.h>

// Problem constants
#define B_SZ  16384
#define F_SZ  64
#define U_SZ  64
#define H1_SZ 64
#define H2_SZ 32

// W2t padded row stride (floats): must be multiple of 4 (16B alignment for
// ulonglong2 LDS.128) -> 68
#define W2T_STRIDE 68

typedef unsigned long long u64t;

__device__ __forceinline__ u64t pk2(float lo, float hi) {
    u64t r;
    asm("mov.b64 %0, {%1, %2};" : "=l"(r) : "f"(lo), "f"(hi));
    return r;
}
__device__ __forceinline__ float2 upk2(u64t v) {
    float2 f;
    asm("mov.b64 {%0, %1}, %2;" : "=f"(f.x), "=f"(f.y) : "l"(v));
    return f;
}
// Packed f32x2 FMA: 2 fp32 FMAs per instruction (sm_100+ only, PTX-only form)
__device__ __forceinline__ u64t ffma2(u64t a, u64t b, u64t c) {
    u64t d;
    asm("fma.rn.f32x2 %0, %1, %2, %3;" : "=l"(d) : "l"(a), "l"(b), "l"(c));
    return d;
}

// One block = one (feature f, tile of 128 batch rows). Each thread owns one row.
__global__ __launch_bounds__(128)
void nam_main_kernel(const float* __restrict__ inputs,
                     const float* __restrict__ W0,
                     const float* __restrict__ b0,
                     const float* __restrict__ W1,
                     const float* __restrict__ b1,
                     const float* __restrict__ W2,
                     const float* __restrict__ b2,
                     const float* __restrict__ Wo,
                     const float* __restrict__ bo,
                     float* __restrict__ out_dropout,  // d_out + B  (B*F)
                     float* __restrict__ out_y)        // d_out + B + B*F (B*F)
{
    __shared__ __align__(16) float s_expW0[U_SZ];
    __shared__ __align__(16) float s_W1[U_SZ * H1_SZ];          // [u][h], h contiguous
    __shared__ __align__(16) float s_W2t[H2_SZ * W2T_STRIDE];   // [h2][h], padded
    __shared__ float s_b1[H1_SZ];
    __shared__ float s_b2[H2_SZ];
    __shared__ float s_Wo[H2_SZ];
    __shared__ float s_b0f, s_bof;

    const int f   = blockIdx.x;
    const int tid = threadIdx.x;

    // ---- stage per-feature weights into smem ----
    if (tid < U_SZ)  s_expW0[tid] = expf(W0[f * U_SZ + tid]);
    #pragma unroll
    for (int i = tid; i < U_SZ * H1_SZ; i += 128)
        s_W1[i] = W1[f * U_SZ * H1_SZ + i];
    #pragma unroll
    for (int i = tid; i < H1_SZ * H2_SZ; i += 128) {
        int h  = i >> 5;       // H2 = 32
        int h2 = i & 31;
        s_W2t[h2 * W2T_STRIDE + h] = W2[f * H1_SZ * H2_SZ + i];
    }
    if (tid < H1_SZ) s_b1[tid] = b1[f * H1_SZ + tid];
    if (tid < H2_SZ) {
        s_b2[tid] = b2[f * H2_SZ + tid];
        s_Wo[tid] = Wo[f * H2_SZ + tid];
    }
    if (tid == 0) { s_b0f = b0[f]; s_bof = bo[f]; }
    __syncthreads();

    const int b = blockIdx.y * 128 + tid;

    // ---- h0 = clip((x - b0) * exp(W0), 0, 1) ----
    const float t = inputs[b * F_SZ + f] - s_b0f;
    float h0[U_SZ];
    #pragma unroll
    for (int u = 0; u < U_SZ; u++)
        h0[u] = __saturatef(t * s_expW0[u]);

    // ---- layer 1: h1[h] = relu(sum_u h0[u] * W1[u][h] + b1[h]) ----
    // packed over h: h1p[i] holds (h1[2i], h1[2i+1])
    u64t h1p[H1_SZ / 2];
    #pragma unroll
    for (int c = 0; c < 2; c++) {            // two chunks of 32 h (16 pairs)
        u64t acc[16];
        #pragma unroll
        for (int i = 0; i < 16; i++)
            acc[i] = pk2(s_b1[c * 32 + 2 * i], s_b1[c * 32 + 2 * i + 1]);
        #pragma unroll
        for (int u = 0; u < U_SZ; u++) {
            const u64t a = pk2(h0[u], h0[u]);
            const ulonglong2* w =
                reinterpret_cast<const ulonglong2*>(&s_W1[u * H1_SZ + c * 32]);
            #pragma unroll
            for (int j = 0; j < 8; j++) {
                ulonglong2 wv = w[j];
                acc[2 * j]     = ffma2(a, wv.x, acc[2 * j]);
                acc[2 * j + 1] = ffma2(a, wv.y, acc[2 * j + 1]);
            }
        }
        #pragma unroll
        for (int i = 0; i < 16; i++) {
            float2 v = upk2(acc[i]);
            h1p[c * 16 + i] = pk2(fmaxf(v.x, 0.f), fmaxf(v.y, 0.f));
        }
    }

    // ---- layer 2 + output dot ----
    // acc2[j] lanes hold partial sums over even/odd h; reduce lanes at end.
    float y = s_bof;
    #pragma unroll
    for (int c = 0; c < 4; c++) {            // four chunks of 8 h2
        u64t acc[8];
        #pragma unroll
        for (int j = 0; j < 8; j++) acc[j] = 0ull;   // (0.f, 0.f)
        #pragma unroll
        for (int i2 = 0; i2 < 16; i2++) {    // 16 x ulonglong2 = 64 h values
            const u64t a0 = h1p[2 * i2];
            const u64t a1 = h1p[2 * i2 + 1];
            #pragma unroll
            for (int j = 0; j < 8; j++) {
                const int h2 = c * 8 + j;
                ulonglong2 wv = *reinterpret_cast<const ulonglong2*>(
                    &s_W2t[h2 * W2T_STRIDE + 4 * i2]);
                acc[j] = ffma2(a0, wv.x, acc[j]);
                acc[j] = ffma2(a1, wv.y, acc[j]);
            }
        }
        #pragma unroll
        for (int j = 0; j < 8; j++) {
            const int h2 = c * 8 + j;
            float2 v = upk2(acc[j]);
            float hv = fmaxf(v.x + v.y + s_b2[h2], 0.f);
            y = fmaf(hv, s_Wo[h2], y);
        }
    }

    const int idx = b * F_SZ + f;
    out_dropout[idx] = y;
    out_y[idx]       = y;
}

// out[b] = bias + sum_f y[b, f]
__global__ __launch_bounds__(256)
void nam_reduce_kernel(const float* __restrict__ y,
                       const float* __restrict__ bias,
                       float* __restrict__ out)
{
    const int b = blockIdx.x * 256 + threadIdx.x;
    const float* row = y + b * F_SZ;
    float s = bias[0];
    #pragma unroll
    for (int f = 0; f < F_SZ; f++) s += row[f];
    out[b] = s;
}

extern "C" void kernel_launch(void* const* d_in, const int* in_sizes, int n_in,
                              void* d_out, int out_size)
{
    const float* inputs = (const float*)d_in[0];
    const float* W0     = (const float*)d_in[1];
    const float* b0     = (const float*)d_in[2];
    const float* W1     = (const float*)d_in[3];
    const float* b1     = (const float*)d_in[4];
    const float* W2     = (const float*)d_in[5];
    const float* b2     = (const float*)d_in[6];
    const float* Wo     = (const float*)d_in[7];
    const float* bo     = (const float*)d_in[8];
    const float* bias   = (const float*)d_in[9];

    float* out          = (float*)d_out;                       // B
    float* out_dropout  = (float*)d_out + B_SZ;                // B*F
    float* out_y        = (float*)d_out + B_SZ + B_SZ * F_SZ;  // B*F

    dim3 grid(F_SZ, B_SZ / 128);
    nam_main_kernel<<<grid, 128>>>(inputs, W0, b0, W1, b1, W2, b2, Wo, bo,
                                   out_dropout, out_y);
    nam_reduce_kernel<<<B_SZ / 256, 256>>>(out_dropout, bias, out);
}

// round 6
// speedup vs baseline: 2.3827x; 2.3827x over previous
#include <cuda_runtime.h>
#include <cuda_bf16.h>
#include <cstdint>

#define B_SZ 16384
#define F_SZ 64

// ---------------------------------------------------------------------------
// Portable (compute_103-safe) tensor-core helpers: ldmatrix + mma.sync (sm_80+)
// ---------------------------------------------------------------------------
__device__ __forceinline__ uint32_t smem_to_u32(const void* smem_ptr) {
    uint32_t addr;
    asm("{ .reg .u64 tmp; cvta.to.shared.u64 tmp, %1; cvt.u32.u64 %0, tmp; }"
        : "=r"(addr) : "l"(smem_ptr));
    return addr;
}

__device__ __forceinline__ void ldsm_x4(uint32_t* r, uint32_t addr) {
    asm volatile(
        "ldmatrix.sync.aligned.m8n8.x4.shared.b16 {%0,%1,%2,%3}, [%4];"
        : "=r"(r[0]), "=r"(r[1]), "=r"(r[2]), "=r"(r[3]) : "r"(addr));
}
__device__ __forceinline__ void ldsm_x4_trans(uint32_t* r, uint32_t addr) {
    asm volatile(
        "ldmatrix.sync.aligned.m8n8.x4.trans.shared.b16 {%0,%1,%2,%3}, [%4];"
        : "=r"(r[0]), "=r"(r[1]), "=r"(r[2]), "=r"(r[3]) : "r"(addr));
}

// D += A * B  (m16n8k16, bf16 in, f32 accum)
__device__ __forceinline__ void mma_bf16(float* d, const uint32_t* a,
                                         const uint32_t* b) {
    asm volatile(
        "mma.sync.aligned.m16n8k16.row.col.f32.bf16.bf16.f32 "
        "{%0,%1,%2,%3}, {%4,%5,%6,%7}, {%8,%9}, {%0,%1,%2,%3};"
        : "+f"(d[0]), "+f"(d[1]), "+f"(d[2]), "+f"(d[3])
        : "r"(a[0]), "r"(a[1]), "r"(a[2]), "r"(a[3]), "r"(b[0]), "r"(b[1]));
}

// Per-lane ldmatrix address for a 16x16 b16 tile at (r0,c0), row stride ld (b16).
// mat0: rows r0+0..7 @c0 | mat1: rows +8 @c0 | mat2: rows 0..7 @c0+8 | mat3: +8,+8
__device__ __forceinline__ uint32_t ldsm_addr(uint32_t base, int r0, int c0,
                                              int ld, int lane) {
    int r = r0 + (lane & 7) + (((lane >> 3) & 1) << 3);
    int c = c0 + ((lane >> 4) << 3);
    return base + (uint32_t)((r * ld + c) * 2);
}

// ---------------------------------------------------------------------------
// SMEM layout (bytes from dynamic base). Strides in bf16 elements:
//   A tiles (h0 / h1): 128 rows x 64 cols, LDA = 72  (144B rows: ldmatrix
//   conflict-free since 36*r + w spans all 32 banks)
//   W1: 64x64, ld 72.   W2: 64x32, ld 40 (80B rows, also conflict-free).
// ---------------------------------------------------------------------------
static constexpr int LDA  = 72;
static constexpr int LDW1 = 72;
static constexpr int LDW2 = 40;

static constexpr int SM_B1   = 0;                    // 64 f32
static constexpr int SM_B2   = 256;                  // 32 f32
static constexpr int SM_WO   = 384;                  // 32 f32
static constexpr int SM_SCAL = 512;                  // b0f, bof
static constexpr int SM_EXPW = 576;                  // 64 f32
static constexpr int SM_A0HI = 1024;                 // 128*72*2 = 18432
static constexpr int SM_A0LO = SM_A0HI + 18432;      // 19456
static constexpr int SM_W1HI = SM_A0LO + 18432;      // 37888 (64*72*2=9216)
static constexpr int SM_W1LO = SM_W1HI + 9216;       // 47104
static constexpr int SM_W2HI = SM_W1LO + 9216;       // 56320 (64*40*2=5120)
static constexpr int SM_W2LO = SM_W2HI + 5120;       // 61440
static constexpr int SMEM_TOTAL = SM_W2LO + 5120;    // 66560

__device__ __forceinline__ void split_store_pair(char* smem, int hi_off,
                                                 int lo_off, float v0, float v1) {
    __nv_bfloat162 hh = __floats2bfloat162_rn(v0, v1);
    __nv_bfloat162 ll = __floats2bfloat162_rn(v0 - __bfloat162float(hh.x),
                                              v1 - __bfloat162float(hh.y));
    *(uint32_t*)(smem + hi_off) = *(uint32_t*)&hh;
    *(uint32_t*)(smem + lo_off) = *(uint32_t*)&ll;
}

__global__ __launch_bounds__(128)
void nam_mma_kernel(const float* __restrict__ inputs,
                    const float* __restrict__ W0,
                    const float* __restrict__ b0,
                    const float* __restrict__ W1,
                    const float* __restrict__ b1,
                    const float* __restrict__ W2,
                    const float* __restrict__ b2,
                    const float* __restrict__ Wo,
                    const float* __restrict__ bo,
                    float* __restrict__ out_dropout,
                    float* __restrict__ out_y)
{
    extern __shared__ char smem[];
    const uint32_t sb = smem_to_u32(smem);
    const int tid  = threadIdx.x;
    const int lane = tid & 31;
    const int warp = tid >> 5;
    const int f    = blockIdx.x;

    // ---- stage per-feature weights (bf16 hi/lo) + vectors ----
    if (tid < 64) {
        ((float*)(smem + SM_EXPW))[tid] = expf(W0[f * 64 + tid]);
        ((float*)(smem + SM_B1))[tid]   = b1[f * 64 + tid];
    }
    if (tid < 32) {
        ((float*)(smem + SM_B2))[tid] = b2[f * 32 + tid];
        ((float*)(smem + SM_WO))[tid] = Wo[f * 32 + tid];
    }
    if (tid == 0) {
        ((float*)(smem + SM_SCAL))[0] = b0[f];
        ((float*)(smem + SM_SCAL))[1] = bo[f];
    }
    {
        const float* W1f = W1 + (size_t)f * 64 * 64;
        #pragma unroll 4
        for (int i = tid; i < 64 * 64; i += 128) {
            float w = W1f[i];
            int u = i >> 6, h = i & 63;            // (k=u, n=h)
            __nv_bfloat16 wh = __float2bfloat16(w);
            __nv_bfloat16 wl = __float2bfloat16(w - __bfloat162float(wh));
            int e = u * LDW1 + h;
            *(__nv_bfloat16*)(smem + SM_W1HI + 2 * e) = wh;
            *(__nv_bfloat16*)(smem + SM_W1LO + 2 * e) = wl;
        }
        const float* W2f = W2 + (size_t)f * 64 * 32;
        #pragma unroll 4
        for (int i = tid; i < 64 * 32; i += 128) {
            float w = W2f[i];
            int h1i = i >> 5, h2i = i & 31;        // (k=h1, n=h2)
            __nv_bfloat16 wh = __float2bfloat16(w);
            __nv_bfloat16 wl = __float2bfloat16(w - __bfloat162float(wh));
            int e = h1i * LDW2 + h2i;
            *(__nv_bfloat16*)(smem + SM_W2HI + 2 * e) = wh;
            *(__nv_bfloat16*)(smem + SM_W2LO + 2 * e) = wl;
        }
    }
    __syncthreads();

    // ---- h0 = clip((x - b0)*exp(W0), 0, 1) -> bf16 hi/lo rows (row = tid) ----
    {
        const float b0f  = ((const float*)(smem + SM_SCAL))[0];
        const float* ew  = (const float*)(smem + SM_EXPW);
        const int row    = blockIdx.y * 128 + tid;
        const float t    = inputs[(size_t)row * F_SZ + f] - b0f;
        #pragma unroll
        for (int u = 0; u < 64; u += 2) {
            float v0 = __saturatef(t * ew[u]);
            float v1 = __saturatef(t * ew[u + 1]);
            int e = (tid * LDA + u) * 2;
            split_store_pair(smem, SM_A0HI + e, SM_A0LO + e, v0, v1);
        }
    }
    __syncwarp();   // each warp consumes only its own 32 rows below

    const int rbase = warp * 32;
    const float* b1v = (const float*)(smem + SM_B1);
    const float* b2v = (const float*)(smem + SM_B2);
    const float* wov = (const float*)(smem + SM_WO);
    const float bof  = ((const float*)(smem + SM_SCAL))[1];
    const int cc0    = 2 * (lane & 3);
    const int rsub   = lane >> 2;

    // =================== layer 1: h1 = relu(h0 @ W1 + b1) ===================
    #pragma unroll
    for (int m = 0; m < 2; m++) {
        const int r0 = rbase + m * 16;
        uint32_t Ah[4][4], Al[4][4];
        #pragma unroll
        for (int k = 0; k < 4; k++) {
            ldsm_x4(Ah[k], ldsm_addr(sb + SM_A0HI, r0, k * 16, LDA, lane));
            ldsm_x4(Al[k], ldsm_addr(sb + SM_A0LO, r0, k * 16, LDA, lane));
        }
        float acc[8][4];
        #pragma unroll
        for (int n = 0; n < 8; n++)
            #pragma unroll
            for (int j = 0; j < 4; j++) acc[n][j] = 0.f;

        #pragma unroll
        for (int np = 0; np < 4; np++) {
            #pragma unroll
            for (int k = 0; k < 4; k++) {
                uint32_t Bh[4], Bl[4];
                ldsm_x4_trans(Bh, ldsm_addr(sb + SM_W1HI, k * 16, np * 16, LDW1, lane));
                ldsm_x4_trans(Bl, ldsm_addr(sb + SM_W1LO, k * 16, np * 16, LDW1, lane));
                mma_bf16(acc[2 * np],     Ah[k], Bh + 0);
                mma_bf16(acc[2 * np + 1], Ah[k], Bh + 2);
                mma_bf16(acc[2 * np],     Ah[k], Bl + 0);
                mma_bf16(acc[2 * np + 1], Ah[k], Bl + 2);
                mma_bf16(acc[2 * np],     Al[k], Bh + 0);
                mma_bf16(acc[2 * np + 1], Al[k], Bh + 2);
            }
        }
        // epilogue 1: relu + bias, split, overwrite A0 rows (consumed above)
        const int rr = r0 + rsub;
        #pragma unroll
        for (int n = 0; n < 8; n++) {
            const int c = n * 8 + cc0;
            float f0 = fmaxf(acc[n][0] + b1v[c],     0.f);
            float f1 = fmaxf(acc[n][1] + b1v[c + 1], 0.f);
            float f2 = fmaxf(acc[n][2] + b1v[c],     0.f);
            float f3 = fmaxf(acc[n][3] + b1v[c + 1], 0.f);
            int e0 = (rr * LDA + c) * 2;
            int e1 = ((rr + 8) * LDA + c) * 2;
            split_store_pair(smem, SM_A0HI + e0, SM_A0LO + e0, f0, f1);
            split_store_pair(smem, SM_A0HI + e1, SM_A0LO + e1, f2, f3);
        }
        __syncwarp();
    }

    // ============ layer 2 + output: y = relu(h1 @ W2 + b2) . Wo + bo ============
    #pragma unroll
    for (int m = 0; m < 2; m++) {
        const int r0 = rbase + m * 16;
        uint32_t Ah[4][4], Al[4][4];
        #pragma unroll
        for (int k = 0; k < 4; k++) {
            ldsm_x4(Ah[k], ldsm_addr(sb + SM_A0HI, r0, k * 16, LDA, lane));
            ldsm_x4(Al[k], ldsm_addr(sb + SM_A0LO, r0, k * 16, LDA, lane));
        }
        float acc[4][4];
        #pragma unroll
        for (int n = 0; n < 4; n++)
            #pragma unroll
            for (int j = 0; j < 4; j++) acc[n][j] = 0.f;

        #pragma unroll
        for (int np = 0; np < 2; np++) {
            #pragma unroll
            for (int k = 0; k < 4; k++) {
                uint32_t Bh[4], Bl[4];
                ldsm_x4_trans(Bh, ldsm_addr(sb + SM_W2HI, k * 16, np * 16, LDW2, lane));
                ldsm_x4_trans(Bl, ldsm_addr(sb + SM_W2LO, k * 16, np * 16, LDW2, lane));
                mma_bf16(acc[2 * np],     Ah[k], Bh + 0);
                mma_bf16(acc[2 * np + 1], Ah[k], Bh + 2);
                mma_bf16(acc[2 * np],     Ah[k], Bl + 0);
                mma_bf16(acc[2 * np + 1], Ah[k], Bl + 2);
                mma_bf16(acc[2 * np],     Al[k], Bh + 0);
                mma_bf16(acc[2 * np + 1], Al[k], Bh + 2);
            }
        }
        // epilogue 2: relu + b2, dot with Wo, quad-reduce, store
        float y0 = 0.f, y1 = 0.f;
        #pragma unroll
        for (int n = 0; n < 4; n++) {
            const int c = n * 8 + cc0;
            y0 = fmaf(fmaxf(acc[n][0] + b2v[c],     0.f), wov[c],     y0);
            y0 = fmaf(fmaxf(acc[n][1] + b2v[c + 1], 0.f), wov[c + 1], y0);
            y1 = fmaf(fmaxf(acc[n][2] + b2v[c],     0.f), wov[c],     y1);
            y1 = fmaf(fmaxf(acc[n][3] + b2v[c + 1], 0.f), wov[c + 1], y1);
        }
        y0 += __shfl_xor_sync(0xffffffffu, y0, 1);
        y0 += __shfl_xor_sync(0xffffffffu, y0, 2);
        y1 += __shfl_xor_sync(0xffffffffu, y1, 1);
        y1 += __shfl_xor_sync(0xffffffffu, y1, 2);
        if ((lane & 3) == 0) {
            const int rg = blockIdx.y * 128 + r0 + rsub;
            const size_t i0 = (size_t)rg * F_SZ + f;
            const size_t i1 = (size_t)(rg + 8) * F_SZ + f;
            out_dropout[i0] = y0 + bof;  out_y[i0] = y0 + bof;
            out_dropout[i1] = y1 + bof;  out_y[i1] = y1 + bof;
        }
    }
}

// out[b] = bias + sum_f y[b,f] — coalesced loads + warp shuffle reduce
__global__ __launch_bounds__(256)
void nam_reduce_kernel(const float* __restrict__ y,
                       const float* __restrict__ bias,
                       float* __restrict__ out)
{
    const int lane = threadIdx.x & 31;
    const int warp = threadIdx.x >> 5;
    const int rowbase = blockIdx.x * 64 + warp * 8;
    const float bb = bias[0];
    #pragma unroll
    for (int r = 0; r < 8; r++) {
        const float* row = y + (size_t)(rowbase + r) * F_SZ;
        float v = row[lane] + row[lane + 32];
        #pragma unroll
        for (int s = 16; s; s >>= 1) v += __shfl_xor_sync(0xffffffffu, v, s);
        if (lane == 0) out[rowbase + r] = v + bb;
    }
}

extern "C" void kernel_launch(void* const* d_in, const int* in_sizes, int n_in,
                              void* d_out, int out_size)
{
    const float* inputs = (const float*)d_in[0];
    const float* W0     = (const float*)d_in[1];
    const float* b0     = (const float*)d_in[2];
    const float* W1     = (const float*)d_in[3];
    const float* b1     = (const float*)d_in[4];
    const float* W2     = (const float*)d_in[5];
    const float* b2     = (const float*)d_in[6];
    const float* Wo     = (const float*)d_in[7];
    const float* bo     = (const float*)d_in[8];
    const float* bias   = (const float*)d_in[9];

    float* out          = (float*)d_out;                       // B
    float* out_dropout  = (float*)d_out + B_SZ;                // B*F
    float* out_y        = (float*)d_out + B_SZ + B_SZ * F_SZ;  // B*F

    cudaFuncSetAttribute(nam_mma_kernel,
                         cudaFuncAttributeMaxDynamicSharedMemorySize, SMEM_TOTAL);

    dim3 grid(F_SZ, B_SZ / 128);
    nam_mma_kernel<<<grid, 128, SMEM_TOTAL>>>(inputs, W0, b0, W1, b1, W2, b2,
                                              Wo, bo, out_dropout, out_y);
    nam_reduce_kernel<<<B_SZ / 64, 256>>>(out_dropout, bias, out);
}

// round 7
// speedup vs baseline: 3.5838x; 1.5041x over previous
#include <cuda_runtime.h>
#include <cuda_bf16.h>
#include <cstdint>

#define B_SZ 16384
#define F_SZ 64
#define TILES_PER_CTA 4

// ---------------------------------------------------------------------------
// Portable (compute_103-safe) tensor-core helpers: ldmatrix + mma.sync (sm_80+)
// ---------------------------------------------------------------------------
__device__ __forceinline__ uint32_t smem_to_u32(const void* smem_ptr) {
    uint32_t addr;
    asm("{ .reg .u64 tmp; cvta.to.shared.u64 tmp, %1; cvt.u32.u64 %0, tmp; }"
        : "=r"(addr) : "l"(smem_ptr));
    return addr;
}

__device__ __forceinline__ void ldsm_x4_trans(uint32_t* r, uint32_t addr) {
    asm volatile(
        "ldmatrix.sync.aligned.m8n8.x4.trans.shared.b16 {%0,%1,%2,%3}, [%4];"
        : "=r"(r[0]), "=r"(r[1]), "=r"(r[2]), "=r"(r[3]) : "r"(addr));
}

// D += A * B  (m16n8k16, bf16 in, f32 accum)
__device__ __forceinline__ void mma_bf16(float* d, const uint32_t* a,
                                         const uint32_t* b) {
    asm volatile(
        "mma.sync.aligned.m16n8k16.row.col.f32.bf16.bf16.f32 "
        "{%0,%1,%2,%3}, {%4,%5,%6,%7}, {%8,%9}, {%0,%1,%2,%3};"
        : "+f"(d[0]), "+f"(d[1]), "+f"(d[2]), "+f"(d[3])
        : "r"(a[0]), "r"(a[1]), "r"(a[2]), "r"(a[3]), "r"(b[0]), "r"(b[1]));
}

// Per-lane ldmatrix address for a 16x16 b16 tile at (r0,c0), row stride ld (b16).
__device__ __forceinline__ uint32_t ldsm_addr(uint32_t base, int r0, int c0,
                                              int ld, int lane) {
    int r = r0 + (lane & 7) + (((lane >> 3) & 1) << 3);
    int c = c0 + ((lane >> 4) << 3);
    return base + (uint32_t)((r * ld + c) * 2);
}

// bf16 hi/lo split of a float pair, packed as bf16x2 words
__device__ __forceinline__ void split2(float v0, float v1,
                                       uint32_t& hi, uint32_t& lo) {
    __nv_bfloat162 hh = __floats2bfloat162_rn(v0, v1);
    __nv_bfloat162 ll = __floats2bfloat162_rn(v0 - __bfloat162float(hh.x),
                                              v1 - __bfloat162float(hh.y));
    hi = *(uint32_t*)&hh;
    lo = *(uint32_t*)&ll;
}

// ---------------------------------------------------------------------------
// SMEM: weights only. LDW1=72 (144B rows), LDW2=40 (80B rows): conflict-free
// for ldmatrix (row-to-row bank advance 36 resp. 20 mod 32 covers all banks).
// ---------------------------------------------------------------------------
static constexpr int LDW1 = 72;
static constexpr int LDW2 = 40;

static constexpr int SM_B1   = 0;       // 64 f32
static constexpr int SM_B2   = 256;     // 32 f32
static constexpr int SM_WO   = 384;     // 32 f32
static constexpr int SM_SCAL = 512;     // b0f, bof
static constexpr int SM_EXPW = 576;     // 64 f32
static constexpr int SM_W1HI = 1024;    // 64*72*2 = 9216
static constexpr int SM_W1LO = 10240;
static constexpr int SM_W2HI = 19456;   // 64*40*2 = 5120
static constexpr int SM_W2LO = 24576;
static constexpr int SMEM_TOTAL = 29696;

__global__ __launch_bounds__(128)
void nam_mma_kernel(const float* __restrict__ inputs,
                    const float* __restrict__ W0,
                    const float* __restrict__ b0,
                    const float* __restrict__ W1,
                    const float* __restrict__ b1,
                    const float* __restrict__ W2,
                    const float* __restrict__ b2,
                    const float* __restrict__ Wo,
                    const float* __restrict__ bo,
                    float* __restrict__ out_dropout,
                    float* __restrict__ out_y)
{
    extern __shared__ char smem[];
    const uint32_t sb = smem_to_u32(smem);
    const int tid  = threadIdx.x;
    const int lane = tid & 31;
    const int warp = tid >> 5;
    const int f    = blockIdx.x;

    // ---- stage per-feature weights (bf16 hi/lo) + vectors, once per CTA ----
    if (tid < 64) {
        ((float*)(smem + SM_EXPW))[tid] = expf(W0[f * 64 + tid]);
        ((float*)(smem + SM_B1))[tid]   = b1[f * 64 + tid];
    }
    if (tid < 32) {
        ((float*)(smem + SM_B2))[tid] = b2[f * 32 + tid];
        ((float*)(smem + SM_WO))[tid] = Wo[f * 32 + tid];
    }
    if (tid == 0) {
        ((float*)(smem + SM_SCAL))[0] = b0[f];
        ((float*)(smem + SM_SCAL))[1] = bo[f];
    }
    {
        const float* W1f = W1 + (size_t)f * 64 * 64;
        #pragma unroll 4
        for (int i = tid; i < 64 * 64; i += 128) {
            float w = W1f[i];
            int u = i >> 6, h = i & 63;            // (k=u, n=h)
            __nv_bfloat16 wh = __float2bfloat16(w);
            __nv_bfloat16 wl = __float2bfloat16(w - __bfloat162float(wh));
            int e = u * LDW1 + h;
            *(__nv_bfloat16*)(smem + SM_W1HI + 2 * e) = wh;
            *(__nv_bfloat16*)(smem + SM_W1LO + 2 * e) = wl;
        }
        const float* W2f = W2 + (size_t)f * 64 * 32;
        #pragma unroll 4
        for (int i = tid; i < 64 * 32; i += 128) {
            float w = W2f[i];
            int h1i = i >> 5, h2i = i & 31;        // (k=h1, n=h2)
            __nv_bfloat16 wh = __float2bfloat16(w);
            __nv_bfloat16 wl = __float2bfloat16(w - __bfloat162float(wh));
            int e = h1i * LDW2 + h2i;
            *(__nv_bfloat16*)(smem + SM_W2HI + 2 * e) = wh;
            *(__nv_bfloat16*)(smem + SM_W2LO + 2 * e) = wl;
        }
    }
    __syncthreads();

    const float* b1v = (const float*)(smem + SM_B1);
    const float* b2v = (const float*)(smem + SM_B2);
    const float* wov = (const float*)(smem + SM_WO);
    const float* ew  = (const float*)(smem + SM_EXPW);
    const float b0f  = ((const float*)(smem + SM_SCAL))[0];
    const float bof  = ((const float*)(smem + SM_SCAL))[1];

    const int q  = lane >> 2;       // fragment row within 8
    const int cc = 2 * (lane & 3);  // fragment col pair base

    #pragma unroll 1
    for (int tl = 0; tl < TILES_PER_CTA; tl++) {
        const int tilebase = (blockIdx.y * TILES_PER_CTA + tl) * 128;
        const float t = inputs[(size_t)(tilebase + tid) * F_SZ + f] - b0f;

        // t values for this warp's two 16-row m-tiles (fragment rows)
        const float tA0 = __shfl_sync(0xffffffffu, t, q);        // m=0, rows q
        const float tA1 = __shfl_sync(0xffffffffu, t, 8 + q);    // m=0, rows q+8
        const float tB0 = __shfl_sync(0xffffffffu, t, 16 + q);   // m=1
        const float tB1 = __shfl_sync(0xffffffffu, t, 24 + q);

        // =================== layer 1: h1 = relu(h0 @ W1 + b1) ===============
        float acc1[2][8][4];
        #pragma unroll
        for (int m = 0; m < 2; m++)
            #pragma unroll
            for (int n = 0; n < 8; n++)
                #pragma unroll
                for (int j = 0; j < 4; j++) acc1[m][n][j] = 0.f;

        #pragma unroll
        for (int k = 0; k < 4; k++) {
            const int c0 = k * 16 + cc;
            const float2 eA = *(const float2*)(ew + c0);
            const float2 eB = *(const float2*)(ew + c0 + 8);

            uint32_t Ah[2][4], Al[2][4];
            #pragma unroll
            for (int m = 0; m < 2; m++) {
                const float tlo = m ? tB0 : tA0;
                const float thi = m ? tB1 : tA1;
                split2(__saturatef(tlo * eA.x), __saturatef(tlo * eA.y),
                       Ah[m][0], Al[m][0]);
                split2(__saturatef(thi * eA.x), __saturatef(thi * eA.y),
                       Ah[m][1], Al[m][1]);
                split2(__saturatef(tlo * eB.x), __saturatef(tlo * eB.y),
                       Ah[m][2], Al[m][2]);
                split2(__saturatef(thi * eB.x), __saturatef(thi * eB.y),
                       Ah[m][3], Al[m][3]);
            }
            #pragma unroll
            for (int np = 0; np < 4; np++) {
                uint32_t Bh[4], Bl[4];
                ldsm_x4_trans(Bh, ldsm_addr(sb + SM_W1HI, k * 16, np * 16, LDW1, lane));
                ldsm_x4_trans(Bl, ldsm_addr(sb + SM_W1LO, k * 16, np * 16, LDW1, lane));
                #pragma unroll
                for (int m = 0; m < 2; m++) {
                    mma_bf16(acc1[m][2 * np],     Ah[m], Bh + 0);
                    mma_bf16(acc1[m][2 * np + 1], Ah[m], Bh + 2);
                    mma_bf16(acc1[m][2 * np],     Ah[m], Bl + 0);
                    mma_bf16(acc1[m][2 * np + 1], Ah[m], Bl + 2);
                    mma_bf16(acc1[m][2 * np],     Al[m], Bh + 0);
                    mma_bf16(acc1[m][2 * np + 1], Al[m], Bh + 2);
                }
            }
        }

        // ====== layer 2: acc1 (D-frag) -> A-frag in registers, no smem ======
        float acc2[2][4][4];
        #pragma unroll
        for (int m = 0; m < 2; m++)
            #pragma unroll
            for (int n = 0; n < 4; n++)
                #pragma unroll
                for (int j = 0; j < 4; j++) acc2[m][n][j] = 0.f;

        #pragma unroll
        for (int j = 0; j < 4; j++) {                // k-tiles of layer 2
            const int cn = j * 16 + cc;
            const float b1a = b1v[cn],     b1b = b1v[cn + 1];
            const float b1c = b1v[cn + 8], b1d = b1v[cn + 9];

            uint32_t Ah[2][4], Al[2][4];
            #pragma unroll
            for (int m = 0; m < 2; m++) {
                const float* d0 = acc1[m][2 * j];
                const float* d1 = acc1[m][2 * j + 1];
                split2(fmaxf(d0[0] + b1a, 0.f), fmaxf(d0[1] + b1b, 0.f),
                       Ah[m][0], Al[m][0]);
                split2(fmaxf(d0[2] + b1a, 0.f), fmaxf(d0[3] + b1b, 0.f),
                       Ah[m][1], Al[m][1]);
                split2(fmaxf(d1[0] + b1c, 0.f), fmaxf(d1[1] + b1d, 0.f),
                       Ah[m][2], Al[m][2]);
                split2(fmaxf(d1[2] + b1c, 0.f), fmaxf(d1[3] + b1d, 0.f),
                       Ah[m][3], Al[m][3]);
            }
            #pragma unroll
            for (int np = 0; np < 2; np++) {
                uint32_t Bh[4], Bl[4];
                ldsm_x4_trans(Bh, ldsm_addr(sb + SM_W2HI, j * 16, np * 16, LDW2, lane));
                ldsm_x4_trans(Bl, ldsm_addr(sb + SM_W2LO, j * 16, np * 16, LDW2, lane));
                #pragma unroll
                for (int m = 0; m < 2; m++) {
                    mma_bf16(acc2[m][2 * np],     Ah[m], Bh + 0);
                    mma_bf16(acc2[m][2 * np + 1], Ah[m], Bh + 2);
                    mma_bf16(acc2[m][2 * np],     Ah[m], Bl + 0);
                    mma_bf16(acc2[m][2 * np + 1], Ah[m], Bl + 2);
                    mma_bf16(acc2[m][2 * np],     Al[m], Bh + 0);
                    mma_bf16(acc2[m][2 * np + 1], Al[m], Bh + 2);
                }
            }
        }

        // ===== epilogue: y = relu(h2 + b2) . Wo + bo, quad-reduce, store =====
        #pragma unroll
        for (int m = 0; m < 2; m++) {
            float y0 = 0.f, y1 = 0.f;
            #pragma unroll
            for (int n = 0; n < 4; n++) {
                const int c = n * 8 + cc;
                y0 = fmaf(fmaxf(acc2[m][n][0] + b2v[c],     0.f), wov[c],     y0);
                y0 = fmaf(fmaxf(acc2[m][n][1] + b2v[c + 1], 0.f), wov[c + 1], y0);
                y1 = fmaf(fmaxf(acc2[m][n][2] + b2v[c],     0.f), wov[c],     y1);
                y1 = fmaf(fmaxf(acc2[m][n][3] + b2v[c + 1], 0.f), wov[c + 1], y1);
            }
            y0 += __shfl_xor_sync(0xffffffffu, y0, 1);
            y0 += __shfl_xor_sync(0xffffffffu, y0, 2);
            y1 += __shfl_xor_sync(0xffffffffu, y1, 1);
            y1 += __shfl_xor_sync(0xffffffffu, y1, 2);
            if ((lane & 3) == 0) {
                const int rg = tilebase + warp * 32 + m * 16 + q;
                const size_t i0 = (size_t)rg * F_SZ + f;
                const size_t i1 = (size_t)(rg + 8) * F_SZ + f;
                out_dropout[i0] = y0 + bof;  out_y[i0] = y0 + bof;
                out_dropout[i1] = y1 + bof;  out_y[i1] = y1 + bof;
            }
        }
    }
}

// out[b] = bias + sum_f y[b,f] — coalesced loads + warp shuffle reduce
__global__ __launch_bounds__(256)
void nam_reduce_kernel(const float* __restrict__ y,
                       const float* __restrict__ bias,
                       float* __restrict__ out)
{
    const int lane = threadIdx.x & 31;
    const int warp = threadIdx.x >> 5;
    const int rowbase = blockIdx.x * 32 + warp * 4;
    const float bb = bias[0];
    #pragma unroll
    for (int r = 0; r < 4; r++) {
        const float* row = y + (size_t)(rowbase + r) * F_SZ;
        float v = row[lane] + row[lane + 32];
        #pragma unroll
        for (int s = 16; s; s >>= 1) v += __shfl_xor_sync(0xffffffffu, v, s);
        if (lane == 0) out[rowbase + r] = v + bb;
    }
}

extern "C" void kernel_launch(void* const* d_in, const int* in_sizes, int n_in,
                              void* d_out, int out_size)
{
    const float* inputs = (const float*)d_in[0];
    const float* W0     = (const float*)d_in[1];
    const float* b0     = (const float*)d_in[2];
    const float* W1     = (const float*)d_in[3];
    const float* b1     = (const float*)d_in[4];
    const float* W2     = (const float*)d_in[5];
    const float* b2     = (const float*)d_in[6];
    const float* Wo     = (const float*)d_in[7];
    const float* bo     = (const float*)d_in[8];
    const float* bias   = (const float*)d_in[9];

    float* out          = (float*)d_out;                       // B
    float* out_dropout  = (float*)d_out + B_SZ;                // B*F
    float* out_y        = (float*)d_out + B_SZ + B_SZ * F_SZ;  // B*F

    cudaFuncSetAttribute(nam_mma_kernel,
                         cudaFuncAttributeMaxDynamicSharedMemorySize, SMEM_TOTAL);

    dim3 grid(F_SZ, B_SZ / (128 * TILES_PER_CTA));
    nam_mma_kernel<<<grid, 128, SMEM_TOTAL>>>(inputs, W0, b0, W1, b1, W2, b2,
                                              Wo, bo, out_dropout, out_y);
    nam_reduce_kernel<<<B_SZ / 32, 256>>>(out_dropout, bias, out);
}

// round 9
// speedup vs baseline: 3.6024x; 1.0052x over previous
#include <cuda_runtime.h>
#include <cuda_bf16.h>
#include <cstdint>

#define B_SZ 16384
#define F_SZ 64
#define ITERS_PER_CTA 8   // 8 iterations x 64 rows = 512 rows per CTA

// ---------------------------------------------------------------------------
// Portable (compute_103-safe) tensor-core helpers: ldmatrix + mma.sync (sm_80+)
// ---------------------------------------------------------------------------
__device__ __forceinline__ uint32_t smem_to_u32(const void* smem_ptr) {
    uint32_t addr;
    asm("{ .reg .u64 tmp; cvta.to.shared.u64 tmp, %1; cvt.u32.u64 %0, tmp; }"
        : "=r"(addr) : "l"(smem_ptr));
    return addr;
}

__device__ __forceinline__ void ldsm_x4_trans(uint32_t* r, uint32_t addr) {
    asm volatile(
        "ldmatrix.sync.aligned.m8n8.x4.trans.shared.b16 {%0,%1,%2,%3}, [%4];"
        : "=r"(r[0]), "=r"(r[1]), "=r"(r[2]), "=r"(r[3]) : "r"(addr));
}

// D += A * B  (m16n8k16, bf16 in, f32 accum)
__device__ __forceinline__ void mma_bf16(float* d, const uint32_t* a,
                                         const uint32_t* b) {
    asm volatile(
        "mma.sync.aligned.m16n8k16.row.col.f32.bf16.bf16.f32 "
        "{%0,%1,%2,%3}, {%4,%5,%6,%7}, {%8,%9}, {%0,%1,%2,%3};"
        : "+f"(d[0]), "+f"(d[1]), "+f"(d[2]), "+f"(d[3])
        : "r"(a[0]), "r"(a[1]), "r"(a[2]), "r"(a[3]), "r"(b[0]), "r"(b[1]));
}

// bf16 hi/lo split of a float pair, packed as bf16x2 words
__device__ __forceinline__ void split2(float v0, float v1,
                                       uint32_t& hi, uint32_t& lo) {
    __nv_bfloat162 hh = __floats2bfloat162_rn(v0, v1);
    __nv_bfloat162 ll = __floats2bfloat162_rn(v0 - __bfloat162float(hh.x),
                                              v1 - __bfloat162float(hh.y));
    hi = *(uint32_t*)&hh;
    lo = *(uint32_t*)&ll;
}

// ---------------------------------------------------------------------------
// SMEM: weights only. LDW1=72 (144B rows), LDW2=40 (80B rows): conflict-free
// for ldmatrix (row-to-row bank advance 36 resp. 20 mod 32 covers all banks).
// ---------------------------------------------------------------------------
static constexpr int LDW1 = 72;
static constexpr int LDW2 = 40;

static constexpr int SM_B1   = 0;       // 64 f32
static constexpr int SM_B2   = 256;     // 32 f32
static constexpr int SM_WO   = 384;     // 32 f32
static constexpr int SM_SCAL = 512;     // b0f, bof
static constexpr int SM_EXPW = 576;     // 64 f32
static constexpr int SM_W1HI = 1024;    // 64*72*2 = 9216
static constexpr int SM_W1LO = 10240;
static constexpr int SM_W2HI = 19456;   // 64*40*2 = 5120
static constexpr int SM_W2LO = 24576;
static constexpr int SMEM_TOTAL = 29696;

__global__ __launch_bounds__(128)
void nam_mma_kernel(const float* __restrict__ inputs,
                    const float* __restrict__ W0,
                    const float* __restrict__ b0,
                    const float* __restrict__ W1,
                    const float* __restrict__ b1,
                    const float* __restrict__ W2,
                    const float* __restrict__ b2,
                    const float* __restrict__ Wo,
                    const float* __restrict__ bo,
                    float* __restrict__ out_dropout,
                    float* __restrict__ out_y)
{
    extern __shared__ char smem[];
    const uint32_t sb = smem_to_u32(smem);
    const int tid  = threadIdx.x;
    const int lane = tid & 31;
    const int warp = tid >> 5;
    const int f    = blockIdx.x;

    // ---- stage per-feature weights (bf16 hi/lo) + vectors, once per CTA ----
    if (tid < 64) {
        ((float*)(smem + SM_EXPW))[tid] = expf(W0[f * 64 + tid]);
        ((float*)(smem + SM_B1))[tid]   = b1[f * 64 + tid];
    }
    if (tid < 32) {
        ((float*)(smem + SM_B2))[tid] = b2[f * 32 + tid];
        ((float*)(smem + SM_WO))[tid] = Wo[f * 32 + tid];
    }
    if (tid == 0) {
        ((float*)(smem + SM_SCAL))[0] = b0[f];
        ((float*)(smem + SM_SCAL))[1] = bo[f];
    }
    {
        const float* W1f = W1 + (size_t)f * 64 * 64;
        #pragma unroll 4
        for (int i = tid; i < 64 * 64; i += 128) {
            float w = W1f[i];
            int u = i >> 6, h = i & 63;            // (k=u, n=h)
            __nv_bfloat16 wh = __float2bfloat16(w);
            __nv_bfloat16 wl = __float2bfloat16(w - __bfloat162float(wh));
            int e = u * LDW1 + h;
            *(__nv_bfloat16*)(smem + SM_W1HI + 2 * e) = wh;
            *(__nv_bfloat16*)(smem + SM_W1LO + 2 * e) = wl;
        }
        const float* W2f = W2 + (size_t)f * 64 * 32;
        #pragma unroll 4
        for (int i = tid; i < 64 * 32; i += 128) {
            float w = W2f[i];
            int h1i = i >> 5, h2i = i & 31;        // (k=h1, n=h2)
            __nv_bfloat16 wh = __float2bfloat16(w);
            __nv_bfloat16 wl = __float2bfloat16(w - __bfloat162float(wh));
            int e = h1i * LDW2 + h2i;
            *(__nv_bfloat16*)(smem + SM_W2HI + 2 * e) = wh;
            *(__nv_bfloat16*)(smem + SM_W2LO + 2 * e) = wl;
        }
    }
    __syncthreads();

    const float* b1v = (const float*)(smem + SM_B1);
    const float* b2v = (const float*)(smem + SM_B2);
    const float* wov = (const float*)(smem + SM_WO);
    const float* ew  = (const float*)(smem + SM_EXPW);
    const float b0f  = ((const float*)(smem + SM_SCAL))[0];
    const float bof  = ((const float*)(smem + SM_SCAL))[1];

    const int q  = lane >> 2;       // fragment row within 8
    const int cc = 2 * (lane & 3);  // fragment col pair base

    // per-lane exp(W0) columns (loop-invariant, 16 regs)
    float2 eA[4], eB[4];
    #pragma unroll
    for (int k = 0; k < 4; k++) {
        eA[k] = *(const float2*)(ew + k * 16 + cc);
        eB[k] = *(const float2*)(ew + k * 16 + 8 + cc);
    }

    #pragma unroll 1
    for (int it = 0; it < ITERS_PER_CTA; it++) {
        const int rowbase = (blockIdx.y * ITERS_PER_CTA + it) * 64 + warp * 16;
        const float t =
            inputs[(size_t)(rowbase + (lane & 15)) * F_SZ + f] - b0f;
        const float t0 = __shfl_sync(0xffffffffu, t, q);       // rows q
        const float t1 = __shfl_sync(0xffffffffu, t, 8 + q);   // rows q+8

        // ========== layer 1: acc1 = b1 + h0 @ W1 (bias folded in init) ======
        float acc1[8][4];
        #pragma unroll
        for (int n = 0; n < 8; n++) {
            const int c = n * 8 + cc;
            acc1[n][0] = acc1[n][2] = b1v[c];
            acc1[n][1] = acc1[n][3] = b1v[c + 1];
        }
        #pragma unroll
        for (int k = 0; k < 4; k++) {
            uint32_t Ah[4], Al[4];
            split2(__saturatef(t0 * eA[k].x), __saturatef(t0 * eA[k].y),
                   Ah[0], Al[0]);
            split2(__saturatef(t1 * eA[k].x), __saturatef(t1 * eA[k].y),
                   Ah[1], Al[1]);
            split2(__saturatef(t0 * eB[k].x), __saturatef(t0 * eB[k].y),
                   Ah[2], Al[2]);
            split2(__saturatef(t1 * eB[k].x), __saturatef(t1 * eB[k].y),
                   Ah[3], Al[3]);
            #pragma unroll
            for (int np = 0; np < 4; np++) {
                uint32_t Bh[4], Bl[4];
                {
                    int r = k * 16 + (lane & 7) + (((lane >> 3) & 1) << 3);
                    int c = np * 16 + ((lane >> 4) << 3);
                    ldsm_x4_trans(Bh, sb + SM_W1HI + (uint32_t)((r * LDW1 + c) * 2));
                    ldsm_x4_trans(Bl, sb + SM_W1LO + (uint32_t)((r * LDW1 + c) * 2));
                }
                mma_bf16(acc1[2 * np],     Ah, Bh + 0);
                mma_bf16(acc1[2 * np + 1], Ah, Bh + 2);
                mma_bf16(acc1[2 * np],     Ah, Bl + 0);
                mma_bf16(acc1[2 * np + 1], Ah, Bl + 2);
                mma_bf16(acc1[2 * np],     Al, Bh + 0);
                mma_bf16(acc1[2 * np + 1], Al, Bh + 2);
            }
        }

        // ========== layer 2: acc2 = b2 + relu(acc1) @ W2 ====================
        float acc2[4][4];
        #pragma unroll
        for (int n2 = 0; n2 < 4; n2++) {
            const int c = n2 * 8 + cc;
            acc2[n2][0] = acc2[n2][2] = b2v[c];
            acc2[n2][1] = acc2[n2][3] = b2v[c + 1];
        }
        #pragma unroll
        for (int j = 0; j < 4; j++) {
            uint32_t Ah[4], Al[4];
            split2(fmaxf(acc1[2 * j][0], 0.f), fmaxf(acc1[2 * j][1], 0.f),
                   Ah[0], Al[0]);
            split2(fmaxf(acc1[2 * j][2], 0.f), fmaxf(acc1[2 * j][3], 0.f),
                   Ah[1], Al[1]);
            split2(fmaxf(acc1[2 * j + 1][0], 0.f), fmaxf(acc1[2 * j + 1][1], 0.f),
                   Ah[2], Al[2]);
            split2(fmaxf(acc1[2 * j + 1][2], 0.f), fmaxf(acc1[2 * j + 1][3], 0.f),
                   Ah[3], Al[3]);
            #pragma unroll
            for (int np = 0; np < 2; np++) {
                uint32_t Bh[4], Bl[4];
                {
                    int r = j * 16 + (lane & 7) + (((lane >> 3) & 1) << 3);
                    int c = np * 16 + ((lane >> 4) << 3);
                    ldsm_x4_trans(Bh, sb + SM_W2HI + (uint32_t)((r * LDW2 + c) * 2));
                    ldsm_x4_trans(Bl, sb + SM_W2LO + (uint32_t)((r * LDW2 + c) * 2));
                }
                mma_bf16(acc2[2 * np],     Ah, Bh + 0);
                mma_bf16(acc2[2 * np + 1], Ah, Bh + 2);
                mma_bf16(acc2[2 * np],     Ah, Bl + 0);
                mma_bf16(acc2[2 * np + 1], Ah, Bl + 2);
                mma_bf16(acc2[2 * np],     Al, Bh + 0);
                mma_bf16(acc2[2 * np + 1], Al, Bh + 2);
            }
        }

        // ===== epilogue: y = relu(acc2) . Wo + bo, quad-reduce, store =======
        float y0 = 0.f, y1 = 0.f;
        #pragma unroll
        for (int n2 = 0; n2 < 4; n2++) {
            const int c = n2 * 8 + cc;
            y0 = fmaf(fmaxf(acc2[n2][0], 0.f), wov[c],     y0);
            y0 = fmaf(fmaxf(acc2[n2][1], 0.f), wov[c + 1], y0);
            y1 = fmaf(fmaxf(acc2[n2][2], 0.f), wov[c],     y1);
            y1 = fmaf(fmaxf(acc2[n2][3], 0.f), wov[c + 1], y1);
        }
        y0 += __shfl_xor_sync(0xffffffffu, y0, 1);
        y0 += __shfl_xor_sync(0xffffffffu, y0, 2);
        y1 += __shfl_xor_sync(0xffffffffu, y1, 1);
        y1 += __shfl_xor_sync(0xffffffffu, y1, 2);
        if ((lane & 3) == 0) {
            const size_t i0 = (size_t)(rowbase + q) * F_SZ + f;
            const size_t i1 = (size_t)(rowbase + 8 + q) * F_SZ + f;
            out_dropout[i0] = y0 + bof;  out_y[i0] = y0 + bof;
            out_dropout[i1] = y1 + bof;  out_y[i1] = y1 + bof;
        }
    }
}

// out[b] = bias + sum_f y[b,f] — float4 loads, 8 lanes per row
__global__ __launch_bounds__(256)
void nam_reduce_kernel(const float* __restrict__ y,
                       const float* __restrict__ bias,
                       float* __restrict__ out)
{
    const int lane = threadIdx.x & 31;
    const int warp = threadIdx.x >> 5;
    const int sub  = lane >> 3;                 // row within warp's 4
    const int j    = lane & 7;                  // 8 lanes per row
    const int row  = blockIdx.x * 32 + warp * 4 + sub;
    const float4* p = (const float4*)(y + (size_t)row * F_SZ) + j;
    float4 a = p[0], b = p[8];
    float v = ((a.x + a.y) + (a.z + a.w)) + ((b.x + b.y) + (b.z + b.w));
    v += __shfl_xor_sync(0xffffffffu, v, 1);
    v += __shfl_xor_sync(0xffffffffu, v, 2);
    v += __shfl_xor_sync(0xffffffffu, v, 4);
    if (j == 0) out[row] = v + bias[0];
}

extern "C" void kernel_launch(void* const* d_in, const int* in_sizes, int n_in,
                              void* d_out, int out_size)
{
    const float* inputs = (const float*)d_in[0];
    const float* W0     = (const float*)d_in[1];
    const float* b0     = (const float*)d_in[2];
    const float* W1     = (const float*)d_in[3];
    const float* b1     = (const float*)d_in[4];
    const float* W2     = (const float*)d_in[5];
    const float* b2     = (const float*)d_in[6];
    const float* Wo     = (const float*)d_in[7];
    const float* bo     = (const float*)d_in[8];
    const float* bias   = (const float*)d_in[9];

    float* out          = (float*)d_out;                       // B
    float* out_dropout  = (float*)d_out + B_SZ;                // B*F
    float* out_y        = (float*)d_out + B_SZ + B_SZ * F_SZ;  // B*F

    cudaFuncSetAttribute(nam_mma_kernel,
                         cudaFuncAttributeMaxDynamicSharedMemorySize, SMEM_TOTAL);

    dim3 grid(F_SZ, B_SZ / (64 * ITERS_PER_CTA));
    nam_mma_kernel<<<grid, 128, SMEM_TOTAL>>>(inputs, W0, b0, W1, b1, W2, b2,
                                              Wo, bo, out_dropout, out_y);
    nam_reduce_kernel<<<B_SZ / 32, 256>>>(out_dropout, bias, out);
}